// round 11
// baseline (speedup 1.0000x reference)
#include <cuda_runtime.h>

#define NN 50000          // nodes
#define E_MAX 1600000
#define D_IN 64
#define HID 128
#define D_OUT 64

// ---------------- scratch (device globals: allocation-free rule) -------------
__device__ __align__(16) float g_agg1[NN * D_IN];   // 12.8 MB
__device__ __align__(16) float g_h1  [NN * HID];    // 25.6 MB
__device__ __align__(16) float g_agg2[NN * HID];    // 25.6 MB
__device__ __align__(16) float g_h2  [NN * HID];    // 25.6 MB
__device__ int   g_cnt[NN];
__device__ float g_inv[NN];
__device__ int   g_rowptr[NN + 1];
__device__ int   g_fill[NN];
__device__ int   g_csr[E_MAX];
__device__ int   g_detect;   // OR of sampled odd 32-bit words of edge_index

// ---------------- packed f32x2 helpers (FFMA2 on sm_103a) --------------------
__device__ __forceinline__ unsigned long long pack2(float lo, float hi) {
    unsigned long long r;
    asm("mov.b64 %0, {%1, %2};" : "=l"(r) : "f"(lo), "f"(hi));
    return r;
}
__device__ __forceinline__ void unpack2(unsigned long long v, float& lo, float& hi) {
    asm("mov.b64 {%0, %1}, %2;" : "=f"(lo), "=f"(hi) : "l"(v));
}
__device__ __forceinline__ void ffma2(unsigned long long& d,
                                      unsigned long long a, unsigned long long b) {
    asm("fma.rn.f32x2 %0, %1, %2, %0;" : "+l"(d) : "l"(a), "l"(b));
}

// ---------------- helpers ----------------------------------------------------
__device__ __forceinline__ int edge_at(const void* ei, long long i, bool is64) {
    if (is64) return (int)__ldg(((const long long*)ei) + i);
    return __ldg(((const int*)ei) + i);
}

// ---------------- zero counters ----------------------------------------------
__global__ void k_zero() {
    int idx = blockIdx.x * blockDim.x + threadIdx.x;
    if (idx < NN) g_cnt[idx] = 0;
    if (idx == 0) g_detect = 0;
}

// ---------------- int32 vs int64 edge dtype detection ------------------------
// If buffer is int64 (values < 2^31, nonneg), every odd 32-bit word is 0.
__global__ void k_detect(const int* __restrict__ w, long long twoE) {
    int t = threadIdx.x;
    int v = 0;
    #pragma unroll
    for (int s = 0; s < 8; s++) {
        long long i = 2LL * (t + s * 256) + 1;
        if (i < twoE) v |= w[i];
    }
    if (v) atomicOr(&g_detect, 1);
}

// ---------------- in-degree histogram ----------------------------------------
__global__ void k_count(const void* __restrict__ ei, int E) {
    bool is64 = (g_detect == 0);
    int idx = blockIdx.x * blockDim.x + threadIdx.x;
    int stride = gridDim.x * blockDim.x;
    for (int e = idx; e < E; e += stride) {
        int dst = edge_at(ei, (long long)E + e, is64);
        atomicAdd(&g_cnt[dst], 1);
    }
}

// ---------------- single-block exclusive scan + inv-degree --------------------
__global__ __launch_bounds__(1024) void k_scan() {
    __shared__ int ssum[1024];
    const int t = threadIdx.x;
    const int CH = (NN + 1023) / 1024;            // 49
    int beg = t * CH;
    int end = beg + CH; if (end > NN) end = NN;
    int s = 0;
    for (int i = beg; i < end; i++) s += g_cnt[i];
    ssum[t] = s;
    __syncthreads();
    for (int off = 1; off < 1024; off <<= 1) {    // Hillis-Steele inclusive scan
        int v = (t >= off) ? ssum[t - off] : 0;
        __syncthreads();
        ssum[t] += v;
        __syncthreads();
    }
    int run = t ? ssum[t - 1] : 0;
    for (int i = beg; i < end; i++) {
        int c = g_cnt[i];
        g_rowptr[i] = run;
        g_fill[i]   = run;
        g_inv[i]    = 1.0f / (float)(c > 1 ? c : 1);
        run += c;
    }
    if (t == 1023) g_rowptr[NN] = ssum[1023];
}

// ---------------- CSR scatter (src ids into dst buckets) ----------------------
__global__ void k_scatter(const void* __restrict__ ei, int E) {
    bool is64 = (g_detect == 0);
    int idx = blockIdx.x * blockDim.x + threadIdx.x;
    int stride = gridDim.x * blockDim.x;
    for (int e = idx; e < E; e += stride) {
        int src = edge_at(ei, e, is64);
        int dst = edge_at(ei, (long long)E + e, is64);
        int pos = atomicAdd(&g_fill[dst], 1);
        g_csr[pos] = src;
    }
}

// ---------------- CSR gather-sum aggregation ----------------------------------
// D floats per row; D/4 lanes per node, one float4 per lane, sum over neighbors.
template <int D>
__global__ void k_gather(const float* __restrict__ feat, float* __restrict__ out) {
    constexpr int TPE = D / 4;                    // 16 or 32 lanes per node
    int gid  = blockIdx.x * blockDim.x + threadIdx.x;
    int node = gid / TPE;
    int lane = gid % TPE;
    if (node >= NN) return;
    int beg = g_rowptr[node], end = g_rowptr[node + 1];
    const float4* f4 = (const float4*)feat;
    float4 a0 = {0.f, 0.f, 0.f, 0.f};
    float4 a1 = {0.f, 0.f, 0.f, 0.f};
    int j = beg;
    for (; j + 2 <= end; j += 2) {
        int s0 = __ldg(&g_csr[j]);
        int s1 = __ldg(&g_csr[j + 1]);
        float4 v0 = f4[(size_t)s0 * TPE + lane];
        float4 v1 = f4[(size_t)s1 * TPE + lane];
        a0.x += v0.x; a0.y += v0.y; a0.z += v0.z; a0.w += v0.w;
        a1.x += v1.x; a1.y += v1.y; a1.z += v1.z; a1.w += v1.w;
    }
    if (j < end) {
        int s = __ldg(&g_csr[j]);
        float4 v = f4[(size_t)s * TPE + lane];
        a0.x += v.x; a0.y += v.y; a0.z += v.z; a0.w += v.w;
    }
    float4 r;
    r.x = a0.x + a1.x; r.y = a0.y + a1.y; r.z = a0.z + a1.z; r.w = a0.w + a1.w;
    ((float4*)out)[(size_t)node * TPE + lane] = r;
}

// ---------------- fused dual-GEMM + bias + relu (packed FFMA2) ----------------
// C[n, 0:OC] = act( scale(n)*A1[n,:K1] @ B1 + A2[n,:K2] @ B2 + bias ),
// scale(n) = g_inv[n] if useInv (mean aggregation) else 1.
// Accumulators are packed row-pairs (f32x2); B tile stored pre-duplicated.
template <int K1, int K2, int OC, bool RELU>
__global__ __launch_bounds__(256) void k_fused(
    const float* __restrict__ A1, const float* __restrict__ A2,
    const float* __restrict__ B1, const float* __restrict__ B2,
    const float* __restrict__ bias, float* __restrict__ C, bool useInv)
{
    constexpr int BN = 64, BK = 32;
    constexpr int CG = OC / 4;        // column groups (32 or 16)
    constexpr int TY = 256 / CG;      // row groups   (8 or 16)
    constexpr int TM = BN / TY;       // rows/thread  (8 or 4)
    constexpr int NP = TM / 2;        // packed row pairs (4 or 2)
    __shared__ __align__(16) float sA[BK][BN];                  // k-major
    __shared__ __align__(16) unsigned long long sB2[BK][OC];    // dup-packed

    const int n0  = blockIdx.x * BN;
    const int tid = threadIdx.x;
    const int tx  = tid % CG;
    const int ty  = tid / CG;

    unsigned long long acc[NP][4] = {};   // bit-zero == (0.f, 0.f)

    auto do_part = [&](const float* A, const float* B, int K, bool scl) {
        for (int kt = 0; kt < K; kt += BK) {
            // A tile: thread loads 8 consecutive k for one row (with mean scale)
            {
                int n  = tid >> 2;
                int kk = (tid & 3) * 8;
                int gn = n0 + n;
                float s = 1.0f;
                const float* row = nullptr;
                if (gn < NN) {
                    row = A + (size_t)gn * K + kt + kk;
                    if (scl) s = g_inv[gn];
                }
                #pragma unroll
                for (int j = 0; j < 8; j++) {
                    float v = row ? row[j] * s : 0.f;
                    sA[kk + j][n] = v;
                }
            }
            // B tile: coalesced load, store duplicated into both f32x2 halves
            {
                #pragma unroll
                for (int i = 0; i < (BK * OC) / 256; i++) {
                    int idx = tid + i * 256;
                    int kr = idx / OC, c = idx % OC;
                    float v = B[(size_t)(kt + kr) * OC + c];
                    sB2[kr][c] = pack2(v, v);
                }
            }
            __syncthreads();
            #pragma unroll
            for (int k = 0; k < BK; k++) {
                // A row-pairs: adjacent rows are adjacent floats in sA[k][:]
                unsigned long long ap2[NP];
                {
                    ulonglong2 a01 = *(const ulonglong2*)&sA[k][ty * TM];
                    ap2[0] = a01.x; ap2[1] = a01.y;
                    if constexpr (TM == 8) {
                        ulonglong2 a23 = *((const ulonglong2*)&sA[k][ty * TM] + 1);
                        ap2[2] = a23.x; ap2[3] = a23.y;
                    }
                }
                // B duplicated pairs for this thread's 4 columns
                ulonglong2 b01 = *(const ulonglong2*)&sB2[k][tx * 4];
                ulonglong2 b23 = *((const ulonglong2*)&sB2[k][tx * 4] + 1);
                unsigned long long bd[4] = {b01.x, b01.y, b23.x, b23.y};
                #pragma unroll
                for (int p = 0; p < NP; p++) {
                    #pragma unroll
                    for (int c = 0; c < 4; c++) ffma2(acc[p][c], ap2[p], bd[c]);
                }
            }
            __syncthreads();
        }
    };

    do_part(A1, B1, K1, useInv);
    if constexpr (K2 > 0) do_part(A2, B2, K2, false);

    const float4 bv = *(const float4*)&bias[tx * 4];
    #pragma unroll
    for (int p = 0; p < NP; p++) {
        int r0 = n0 + ty * TM + 2 * p;
        float4 o0, o1;
        unpack2(acc[p][0], o0.x, o1.x);
        unpack2(acc[p][1], o0.y, o1.y);
        unpack2(acc[p][2], o0.z, o1.z);
        unpack2(acc[p][3], o0.w, o1.w);
        o0.x += bv.x; o0.y += bv.y; o0.z += bv.z; o0.w += bv.w;
        o1.x += bv.x; o1.y += bv.y; o1.z += bv.z; o1.w += bv.w;
        if (RELU) {
            o0.x = fmaxf(o0.x, 0.f); o0.y = fmaxf(o0.y, 0.f);
            o0.z = fmaxf(o0.z, 0.f); o0.w = fmaxf(o0.w, 0.f);
            o1.x = fmaxf(o1.x, 0.f); o1.y = fmaxf(o1.y, 0.f);
            o1.z = fmaxf(o1.z, 0.f); o1.w = fmaxf(o1.w, 0.f);
        }
        if (r0 < NN)     *(float4*)&C[(size_t)r0 * OC + tx * 4]       = o0;
        if (r0 + 1 < NN) *(float4*)&C[(size_t)(r0 + 1) * OC + tx * 4] = o1;
    }
}

// ---------------- launch ------------------------------------------------------
extern "C" void kernel_launch(void* const* d_in, const int* in_sizes, int n_in,
                              void* d_out, int out_size) {
    const float* x     = (const float*)d_in[0];
    const void*  ei    = d_in[1];
    const float* W_l1  = (const float*)d_in[2];
    const float* b_l1  = (const float*)d_in[3];
    const float* W_r1  = (const float*)d_in[4];
    const float* W_l2  = (const float*)d_in[5];
    const float* b_l2  = (const float*)d_in[6];
    const float* W_r2  = (const float*)d_in[7];
    const float* W_out = (const float*)d_in[8];
    const float* b_out = (const float*)d_in[9];
    float* out = (float*)d_out;

    long long twoE = (long long)in_sizes[1];
    int E = (int)(twoE / 2);

    float *agg1, *agg2, *h1, *h2;
    cudaGetSymbolAddress((void**)&agg1, g_agg1);
    cudaGetSymbolAddress((void**)&agg2, g_agg2);
    cudaGetSymbolAddress((void**)&h1,   g_h1);
    cudaGetSymbolAddress((void**)&h2,   g_h2);

    const int NB = (NN + 63) / 64;   // 782 GEMM blocks

    // ---- build CSR once (shared by both layers) ----
    k_zero   <<<(NN + 255) / 256, 256>>>();
    k_detect <<<1, 256>>>((const int*)ei, twoE);
    k_count  <<<1024, 256>>>(ei, E);
    k_scan   <<<1, 1024>>>();
    k_scatter<<<2048, 256>>>(ei, E);

    // layer 1: agg1 = sum_nbr x ;  h1 = relu(mean*W_l1 + x*W_r1 + b_l1)
    k_gather<D_IN><<<(NN * (D_IN / 4) + 255) / 256, 256>>>(x, agg1);
    k_fused<D_IN, D_IN, HID, true><<<NB, 256>>>(agg1, x, W_l1, W_r1, b_l1, h1, true);

    // layer 2: agg2 = sum_nbr h1 ; h2 = relu(mean*W_l2 + h1*W_r2 + b_l2)
    k_gather<HID><<<(NN * (HID / 4) + 255) / 256, 256>>>(h1, agg2);
    k_fused<HID, HID, HID, true><<<NB, 256>>>(agg2, h1, W_l2, W_r2, b_l2, h2, true);

    // output projection (no relu, no mean scaling)
    k_fused<HID, 0, D_OUT, false><<<NB, 256>>>(h2, nullptr, W_out, nullptr, b_out, out, false);
}

// round 13
// speedup vs baseline: 1.2184x; 1.2184x over previous
#include <cuda_runtime.h>

#define NN 50000          // nodes
#define E_MAX 1600000
#define D_IN 64
#define HID 128
#define D_OUT 64
#define SCAN_BLKS ((NN + 255) / 256)   // 196

// ---------------- scratch (device globals: allocation-free rule) -------------
__device__ __align__(16) float g_agg1[NN * D_IN];   // 12.8 MB
__device__ __align__(16) float g_h1  [NN * HID];    // 25.6 MB
__device__ __align__(16) float g_agg2[NN * HID];    // 25.6 MB
__device__ __align__(16) float g_h2  [NN * HID];    // 25.6 MB
__device__ int   g_cnt[NN];
__device__ float g_inv[NN];
__device__ int   g_rowptr[NN + 1];
__device__ int   g_fill[NN];
__device__ int   g_pre[NN];          // exclusive-within-block prefix
__device__ int   g_blk[SCAN_BLKS];   // per-block totals -> exclusive offsets
__device__ int   g_csr[E_MAX];
__device__ int   g_detect;   // OR of sampled odd 32-bit words of edge_index

// ---------------- packed f32x2 helpers (FFMA2 on sm_103a) --------------------
__device__ __forceinline__ unsigned long long pack2(float lo, float hi) {
    unsigned long long r;
    asm("mov.b64 %0, {%1, %2};" : "=l"(r) : "f"(lo), "f"(hi));
    return r;
}
__device__ __forceinline__ void unpack2(unsigned long long v, float& lo, float& hi) {
    asm("mov.b64 {%0, %1}, %2;" : "=f"(lo), "=f"(hi) : "l"(v));
}
__device__ __forceinline__ void ffma2(unsigned long long& d,
                                      unsigned long long a, unsigned long long b) {
    asm("fma.rn.f32x2 %0, %1, %2, %0;" : "+l"(d) : "l"(a), "l"(b));
}

// ---------------- helpers ----------------------------------------------------
__device__ __forceinline__ int edge_at(const void* ei, long long i, bool is64) {
    if (is64) return (int)__ldg(((const long long*)ei) + i);
    return __ldg(((const int*)ei) + i);
}

// ---------------- zero counters ----------------------------------------------
__global__ void k_zero() {
    int idx = blockIdx.x * blockDim.x + threadIdx.x;
    if (idx < NN) g_cnt[idx] = 0;
    if (idx == 0) g_detect = 0;
}

// ---------------- int32 vs int64 edge dtype detection ------------------------
// If buffer is int64 (values < 2^31, nonneg), every odd 32-bit word is 0.
__global__ void k_detect(const int* __restrict__ w, long long twoE) {
    int t = threadIdx.x;
    int v = 0;
    #pragma unroll
    for (int s = 0; s < 8; s++) {
        long long i = 2LL * (t + s * 256) + 1;
        if (i < twoE) v |= w[i];
    }
    if (v) atomicOr(&g_detect, 1);
}

// ---------------- in-degree histogram ----------------------------------------
__global__ void k_count(const void* __restrict__ ei, int E) {
    bool is64 = (g_detect == 0);
    int idx = blockIdx.x * blockDim.x + threadIdx.x;
    int stride = gridDim.x * blockDim.x;
    for (int e = idx; e < E; e += stride) {
        int dst = edge_at(ei, (long long)E + e, is64);
        atomicAdd(&g_cnt[dst], 1);
    }
}

// ---------------- three-phase parallel scan of g_cnt --------------------------
// Phase 1: block-local inclusive scan; write exclusive-within-block prefix and
// per-block total. Coalesced 256-wide.
__global__ __launch_bounds__(256) void k_scan1() {
    __shared__ int s[256];
    int t = threadIdx.x;
    int i = blockIdx.x * 256 + t;
    int v = (i < NN) ? g_cnt[i] : 0;
    s[t] = v;
    __syncthreads();
    #pragma unroll
    for (int off = 1; off < 256; off <<= 1) {
        int u = (t >= off) ? s[t - off] : 0;
        __syncthreads();
        s[t] += u;
        __syncthreads();
    }
    if (i < NN) g_pre[i] = s[t] - v;
    if (t == 255) g_blk[blockIdx.x] = s[255];
}

// Phase 2: scan the 196 block totals (exclusive), write grand total.
__global__ __launch_bounds__(256) void k_scan2() {
    __shared__ int s[256];
    int t = threadIdx.x;
    int v = (t < SCAN_BLKS) ? g_blk[t] : 0;
    s[t] = v;
    __syncthreads();
    #pragma unroll
    for (int off = 1; off < 256; off <<= 1) {
        int u = (t >= off) ? s[t - off] : 0;
        __syncthreads();
        s[t] += u;
        __syncthreads();
    }
    if (t < SCAN_BLKS) g_blk[t] = s[t] - v;          // exclusive offset
    if (t == 255) g_rowptr[NN] = s[255];             // total = E
}

// Phase 3: add-back; emit rowptr / fill / inv in one coalesced pass.
__global__ __launch_bounds__(256) void k_scan3() {
    int i = blockIdx.x * 256 + threadIdx.x;
    if (i >= NN) return;
    int rp = g_pre[i] + g_blk[i >> 8];
    g_rowptr[i] = rp;
    g_fill[i]   = rp;
    int c = g_cnt[i];
    g_inv[i] = 1.0f / (float)(c > 1 ? c : 1);
}

// ---------------- CSR scatter (src ids into dst buckets) ----------------------
__global__ void k_scatter(const void* __restrict__ ei, int E) {
    bool is64 = (g_detect == 0);
    int idx = blockIdx.x * blockDim.x + threadIdx.x;
    int stride = gridDim.x * blockDim.x;
    for (int e = idx; e < E; e += stride) {
        int src = edge_at(ei, e, is64);
        int dst = edge_at(ei, (long long)E + e, is64);
        int pos = atomicAdd(&g_fill[dst], 1);
        g_csr[pos] = src;
    }
}

// ---------------- CSR gather-sum aggregation ----------------------------------
// D floats per row; D/4 lanes per node, one float4 per lane, sum over neighbors.
template <int D>
__global__ void k_gather(const float* __restrict__ feat, float* __restrict__ out) {
    constexpr int TPE = D / 4;                    // 16 or 32 lanes per node
    int gid  = blockIdx.x * blockDim.x + threadIdx.x;
    int node = gid / TPE;
    int lane = gid % TPE;
    if (node >= NN) return;
    int beg = g_rowptr[node], end = g_rowptr[node + 1];
    const float4* f4 = (const float4*)feat;
    float4 a0 = {0.f, 0.f, 0.f, 0.f};
    float4 a1 = {0.f, 0.f, 0.f, 0.f};
    int j = beg;
    for (; j + 2 <= end; j += 2) {
        int s0 = __ldg(&g_csr[j]);
        int s1 = __ldg(&g_csr[j + 1]);
        float4 v0 = f4[(size_t)s0 * TPE + lane];
        float4 v1 = f4[(size_t)s1 * TPE + lane];
        a0.x += v0.x; a0.y += v0.y; a0.z += v0.z; a0.w += v0.w;
        a1.x += v1.x; a1.y += v1.y; a1.z += v1.z; a1.w += v1.w;
    }
    if (j < end) {
        int s = __ldg(&g_csr[j]);
        float4 v = f4[(size_t)s * TPE + lane];
        a0.x += v.x; a0.y += v.y; a0.z += v.z; a0.w += v.w;
    }
    float4 r;
    r.x = a0.x + a1.x; r.y = a0.y + a1.y; r.z = a0.z + a1.z; r.w = a0.w + a1.w;
    ((float4*)out)[(size_t)node * TPE + lane] = r;
}

// ---------------- fused dual-GEMM + bias + relu (packed FFMA2) ----------------
// C[n, 0:OC] = act( scale(n)*A1[n,:K1] @ B1 + A2[n,:K2] @ B2 + bias ),
// scale(n) = g_inv[n] if useInv (mean aggregation) else 1.
// Accumulators are packed row-pairs (f32x2); B tile stored pre-duplicated.
template <int K1, int K2, int OC, bool RELU>
__global__ __launch_bounds__(256) void k_fused(
    const float* __restrict__ A1, const float* __restrict__ A2,
    const float* __restrict__ B1, const float* __restrict__ B2,
    const float* __restrict__ bias, float* __restrict__ C, bool useInv)
{
    constexpr int BN = 64, BK = 32;
    constexpr int CG = OC / 4;        // column groups (32 or 16)
    constexpr int TY = 256 / CG;      // row groups   (8 or 16)
    constexpr int TM = BN / TY;       // rows/thread  (8 or 4)
    constexpr int NP = TM / 2;        // packed row pairs (4 or 2)
    __shared__ __align__(16) float sA[BK][BN];                  // k-major
    __shared__ __align__(16) unsigned long long sB2[BK][OC];    // dup-packed

    const int n0  = blockIdx.x * BN;
    const int tid = threadIdx.x;
    const int tx  = tid % CG;
    const int ty  = tid / CG;

    unsigned long long acc[NP][4] = {};   // bit-zero == (0.f, 0.f)

    auto do_part = [&](const float* A, const float* B, int K, bool scl) {
        for (int kt = 0; kt < K; kt += BK) {
            // A tile: thread loads 8 consecutive k for one row (with mean scale)
            {
                int n  = tid >> 2;
                int kk = (tid & 3) * 8;
                int gn = n0 + n;
                float s = 1.0f;
                const float* row = nullptr;
                if (gn < NN) {
                    row = A + (size_t)gn * K + kt + kk;
                    if (scl) s = g_inv[gn];
                }
                #pragma unroll
                for (int j = 0; j < 8; j++) {
                    float v = row ? row[j] * s : 0.f;
                    sA[kk + j][n] = v;
                }
            }
            // B tile: coalesced load, store duplicated into both f32x2 halves
            {
                #pragma unroll
                for (int i = 0; i < (BK * OC) / 256; i++) {
                    int idx = tid + i * 256;
                    int kr = idx / OC, c = idx % OC;
                    float v = B[(size_t)(kt + kr) * OC + c];
                    sB2[kr][c] = pack2(v, v);
                }
            }
            __syncthreads();
            #pragma unroll
            for (int k = 0; k < BK; k++) {
                // A row-pairs: adjacent rows are adjacent floats in sA[k][:]
                unsigned long long ap2[NP];
                {
                    ulonglong2 a01 = *(const ulonglong2*)&sA[k][ty * TM];
                    ap2[0] = a01.x; ap2[1] = a01.y;
                    if constexpr (TM == 8) {
                        ulonglong2 a23 = *((const ulonglong2*)&sA[k][ty * TM] + 1);
                        ap2[2] = a23.x; ap2[3] = a23.y;
                    }
                }
                // B duplicated pairs for this thread's 4 columns
                ulonglong2 b01 = *(const ulonglong2*)&sB2[k][tx * 4];
                ulonglong2 b23 = *((const ulonglong2*)&sB2[k][tx * 4] + 1);
                unsigned long long bd[4] = {b01.x, b01.y, b23.x, b23.y};
                #pragma unroll
                for (int p = 0; p < NP; p++) {
                    #pragma unroll
                    for (int c = 0; c < 4; c++) ffma2(acc[p][c], ap2[p], bd[c]);
                }
            }
            __syncthreads();
        }
    };

    do_part(A1, B1, K1, useInv);
    if constexpr (K2 > 0) do_part(A2, B2, K2, false);

    const float4 bv = *(const float4*)&bias[tx * 4];
    #pragma unroll
    for (int p = 0; p < NP; p++) {
        int r0 = n0 + ty * TM + 2 * p;
        float4 o0, o1;
        unpack2(acc[p][0], o0.x, o1.x);
        unpack2(acc[p][1], o0.y, o1.y);
        unpack2(acc[p][2], o0.z, o1.z);
        unpack2(acc[p][3], o0.w, o1.w);
        o0.x += bv.x; o0.y += bv.y; o0.z += bv.z; o0.w += bv.w;
        o1.x += bv.x; o1.y += bv.y; o1.z += bv.z; o1.w += bv.w;
        if (RELU) {
            o0.x = fmaxf(o0.x, 0.f); o0.y = fmaxf(o0.y, 0.f);
            o0.z = fmaxf(o0.z, 0.f); o0.w = fmaxf(o0.w, 0.f);
            o1.x = fmaxf(o1.x, 0.f); o1.y = fmaxf(o1.y, 0.f);
            o1.z = fmaxf(o1.z, 0.f); o1.w = fmaxf(o1.w, 0.f);
        }
        if (r0 < NN)     *(float4*)&C[(size_t)r0 * OC + tx * 4]       = o0;
        if (r0 + 1 < NN) *(float4*)&C[(size_t)(r0 + 1) * OC + tx * 4] = o1;
    }
}

// ---------------- launch ------------------------------------------------------
extern "C" void kernel_launch(void* const* d_in, const int* in_sizes, int n_in,
                              void* d_out, int out_size) {
    const float* x     = (const float*)d_in[0];
    const void*  ei    = d_in[1];
    const float* W_l1  = (const float*)d_in[2];
    const float* b_l1  = (const float*)d_in[3];
    const float* W_r1  = (const float*)d_in[4];
    const float* W_l2  = (const float*)d_in[5];
    const float* b_l2  = (const float*)d_in[6];
    const float* W_r2  = (const float*)d_in[7];
    const float* W_out = (const float*)d_in[8];
    const float* b_out = (const float*)d_in[9];
    float* out = (float*)d_out;

    long long twoE = (long long)in_sizes[1];
    int E = (int)(twoE / 2);

    float *agg1, *agg2, *h1, *h2;
    cudaGetSymbolAddress((void**)&agg1, g_agg1);
    cudaGetSymbolAddress((void**)&agg2, g_agg2);
    cudaGetSymbolAddress((void**)&h1,   g_h1);
    cudaGetSymbolAddress((void**)&h2,   g_h2);

    const int NB = (NN + 63) / 64;   // 782 GEMM blocks

    // ---- build CSR once (shared by both layers) ----
    k_zero   <<<SCAN_BLKS, 256>>>();
    k_detect <<<1, 256>>>((const int*)ei, twoE);
    k_count  <<<1024, 256>>>(ei, E);
    k_scan1  <<<SCAN_BLKS, 256>>>();
    k_scan2  <<<1, 256>>>();
    k_scan3  <<<SCAN_BLKS, 256>>>();
    k_scatter<<<2048, 256>>>(ei, E);

    // layer 1: agg1 = sum_nbr x ;  h1 = relu(mean*W_l1 + x*W_r1 + b_l1)
    k_gather<D_IN><<<(NN * (D_IN / 4) + 255) / 256, 256>>>(x, agg1);
    k_fused<D_IN, D_IN, HID, true><<<NB, 256>>>(agg1, x, W_l1, W_r1, b_l1, h1, true);

    // layer 2: agg2 = sum_nbr h1 ; h2 = relu(mean*W_l2 + h1*W_r2 + b_l2)
    k_gather<HID><<<(NN * (HID / 4) + 255) / 256, 256>>>(h1, agg2);
    k_fused<HID, HID, HID, true><<<NB, 256>>>(agg2, h1, W_l2, W_r2, b_l2, h2, true);

    // output projection (no relu, no mean scaling)
    k_fused<HID, 0, D_OUT, false><<<NB, 256>>>(h2, nullptr, W_out, nullptr, b_out, out, false);
}

// round 14
// speedup vs baseline: 1.2917x; 1.0601x over previous
#include <cuda_runtime.h>

#define NN 50000          // nodes
#define E_MAX 1600000
#define D_IN 64
#define HID 128
#define D_OUT 64
#define SCAN_BLKS ((NN + 255) / 256)   // 196

// ---------------- scratch (device globals: allocation-free rule) -------------
__device__ __align__(16) float g_agg1[NN * D_IN];   // 12.8 MB
__device__ __align__(16) float g_h1  [NN * HID];    // 25.6 MB
__device__ __align__(16) float g_agg2[NN * HID];    // 25.6 MB
__device__ __align__(16) float g_h2  [NN * HID];    // 25.6 MB
__device__ int   g_cnt[NN];
__device__ float g_inv[NN];
__device__ int   g_rowptr[NN + 1];
__device__ int   g_fill[NN];
__device__ int   g_pre[NN];          // exclusive-within-block prefix
__device__ int   g_blk[SCAN_BLKS];   // per-block totals -> exclusive offsets
__device__ int   g_csr[E_MAX];
__device__ int   g_detect;   // 1 if edge_index is int32, 0 if int64

// ---------------- packed f32x2 helpers (FFMA2 on sm_103a) --------------------
__device__ __forceinline__ unsigned long long pack2(float lo, float hi) {
    unsigned long long r;
    asm("mov.b64 %0, {%1, %2};" : "=l"(r) : "f"(lo), "f"(hi));
    return r;
}
__device__ __forceinline__ void unpack2(unsigned long long v, float& lo, float& hi) {
    asm("mov.b64 {%0, %1}, %2;" : "=f"(lo), "=f"(hi) : "l"(v));
}
__device__ __forceinline__ void ffma2(unsigned long long& d,
                                      unsigned long long a, unsigned long long b) {
    asm("fma.rn.f32x2 %0, %1, %2, %0;" : "+l"(d) : "l"(a), "l"(b));
}

// ---------------- helpers ----------------------------------------------------
__device__ __forceinline__ int edge_at(const void* ei, long long i, bool is64) {
    if (is64) return (int)__ldg(((const long long*)ei) + i);
    return __ldg(((const int*)ei) + i);
}

// ---------------- zero counters + int32/int64 detection -----------------------
// Block SCAN_BLKS does the dtype detection alone (no cross-block race on
// g_detect: only this block writes it, as a full value, every run).
// If buffer is int64 (values < 2^31, nonneg), every odd 32-bit word is 0.
__global__ void k_zero(const int* __restrict__ w, long long twoE) {
    if (blockIdx.x == SCAN_BLKS) {
        int t = threadIdx.x;
        int v = 0;
        #pragma unroll
        for (int s = 0; s < 8; s++) {
            long long i = 2LL * (t + s * 256) + 1;
            if (i < twoE) v |= w[i];
        }
        int any = __syncthreads_or(v);
        if (t == 0) g_detect = any ? 1 : 0;
        return;
    }
    int idx = blockIdx.x * 256 + threadIdx.x;
    if (idx < NN) g_cnt[idx] = 0;
}

// ---------------- in-degree histogram ----------------------------------------
__global__ void k_count(const void* __restrict__ ei, int E) {
    bool is64 = (g_detect == 0);
    int idx = blockIdx.x * blockDim.x + threadIdx.x;
    int stride = gridDim.x * blockDim.x;
    for (int e = idx; e < E; e += stride) {
        int dst = edge_at(ei, (long long)E + e, is64);
        atomicAdd(&g_cnt[dst], 1);
    }
}

// ---------------- three-phase parallel scan of g_cnt --------------------------
__global__ __launch_bounds__(256) void k_scan1() {
    __shared__ int s[256];
    int t = threadIdx.x;
    int i = blockIdx.x * 256 + t;
    int v = (i < NN) ? g_cnt[i] : 0;
    s[t] = v;
    __syncthreads();
    #pragma unroll
    for (int off = 1; off < 256; off <<= 1) {
        int u = (t >= off) ? s[t - off] : 0;
        __syncthreads();
        s[t] += u;
        __syncthreads();
    }
    if (i < NN) g_pre[i] = s[t] - v;
    if (t == 255) g_blk[blockIdx.x] = s[255];
}

__global__ __launch_bounds__(256) void k_scan2() {
    __shared__ int s[256];
    int t = threadIdx.x;
    int v = (t < SCAN_BLKS) ? g_blk[t] : 0;
    s[t] = v;
    __syncthreads();
    #pragma unroll
    for (int off = 1; off < 256; off <<= 1) {
        int u = (t >= off) ? s[t - off] : 0;
        __syncthreads();
        s[t] += u;
        __syncthreads();
    }
    if (t < SCAN_BLKS) g_blk[t] = s[t] - v;          // exclusive offset
    if (t == 255) g_rowptr[NN] = s[255];             // total = E
}

__global__ __launch_bounds__(256) void k_scan3() {
    int i = blockIdx.x * 256 + threadIdx.x;
    if (i >= NN) return;
    int rp = g_pre[i] + g_blk[i >> 8];
    g_rowptr[i] = rp;
    g_fill[i]   = rp;
    int c = g_cnt[i];
    g_inv[i] = 1.0f / (float)(c > 1 ? c : 1);
}

// ---------------- CSR scatter (src ids into dst buckets) ----------------------
__global__ void k_scatter(const void* __restrict__ ei, int E) {
    bool is64 = (g_detect == 0);
    int idx = blockIdx.x * blockDim.x + threadIdx.x;
    int stride = gridDim.x * blockDim.x;
    for (int e = idx; e < E; e += stride) {
        int src = edge_at(ei, e, is64);
        int dst = edge_at(ei, (long long)E + e, is64);
        int pos = atomicAdd(&g_fill[dst], 1);
        g_csr[pos] = src;
    }
}

// ---------------- CSR gather-MEAN aggregation ---------------------------------
// D floats per row; D/4 lanes per node, float4 per lane. Writes mean directly
// (pre-scaled by g_inv) so the GEMM needs no per-row scaling. 4-way MLP unroll.
template <int D>
__global__ void k_gather(const float* __restrict__ feat, float* __restrict__ out) {
    constexpr int TPE = D / 4;                    // 16 or 32 lanes per node
    int gid  = blockIdx.x * blockDim.x + threadIdx.x;
    int node = gid / TPE;
    int lane = gid % TPE;
    if (node >= NN) return;
    int beg = g_rowptr[node], end = g_rowptr[node + 1];
    const float4* f4 = (const float4*)feat;
    float4 a0 = {0.f, 0.f, 0.f, 0.f};
    float4 a1 = a0, a2 = a0, a3 = a0;
    int j = beg;
    for (; j + 4 <= end; j += 4) {
        int s0 = __ldg(&g_csr[j]);
        int s1 = __ldg(&g_csr[j + 1]);
        int s2 = __ldg(&g_csr[j + 2]);
        int s3 = __ldg(&g_csr[j + 3]);
        float4 v0 = f4[(size_t)s0 * TPE + lane];
        float4 v1 = f4[(size_t)s1 * TPE + lane];
        float4 v2 = f4[(size_t)s2 * TPE + lane];
        float4 v3 = f4[(size_t)s3 * TPE + lane];
        a0.x += v0.x; a0.y += v0.y; a0.z += v0.z; a0.w += v0.w;
        a1.x += v1.x; a1.y += v1.y; a1.z += v1.z; a1.w += v1.w;
        a2.x += v2.x; a2.y += v2.y; a2.z += v2.z; a2.w += v2.w;
        a3.x += v3.x; a3.y += v3.y; a3.z += v3.z; a3.w += v3.w;
    }
    for (; j < end; j++) {
        int s = __ldg(&g_csr[j]);
        float4 v = f4[(size_t)s * TPE + lane];
        a0.x += v.x; a0.y += v.y; a0.z += v.z; a0.w += v.w;
    }
    float inv = g_inv[node];
    float4 r;
    r.x = ((a0.x + a1.x) + (a2.x + a3.x)) * inv;
    r.y = ((a0.y + a1.y) + (a2.y + a3.y)) * inv;
    r.z = ((a0.z + a1.z) + (a2.z + a3.z)) * inv;
    r.w = ((a0.w + a1.w) + (a2.w + a3.w)) * inv;
    ((float4*)out)[(size_t)node * TPE + lane] = r;
}

// ---------------- fused dual-GEMM + bias + relu (FFMA2, double-buffered) ------
// C[n, 0:OC] = act( A1[n,:K1] @ B1 + A2[n,:K2] @ B2 + bias ).
// Single unified loop over virtual K = K1+K2 (each BK chunk lies fully in one
// part since K1 % BK == 0). Next tile prefetched into registers during math.
template <int K1, int K2, int OC, bool RELU>
__global__ __launch_bounds__(256) void k_fused(
    const float* __restrict__ A1, const float* __restrict__ A2,
    const float* __restrict__ B1, const float* __restrict__ B2,
    const float* __restrict__ bias, float* __restrict__ C)
{
    constexpr int BN = 64, BK = 32;
    constexpr int K  = K1 + K2;
    constexpr int CG = OC / 4;        // column groups (32 or 16)
    constexpr int TY = 256 / CG;      // row groups   (8 or 16)
    constexpr int TM = BN / TY;       // rows/thread  (8 or 4)
    constexpr int NP = TM / 2;        // packed row pairs (4 or 2)
    constexpr int BL = (BK * OC) / 256;   // B floats/thread (16 or 8)
    __shared__ __align__(16) float sA[BK][BN];                  // k-major
    __shared__ __align__(16) unsigned long long sB2[BK][OC];    // dup-packed

    const int n0  = blockIdx.x * BN;
    const int tid = threadIdx.x;
    const int tx  = tid % CG;
    const int ty  = tid / CG;

    const int an  = tid >> 2;         // A row within tile
    const int akk = (tid & 3) * 8;    // A k-offset within tile
    const int gn  = n0 + an;

    unsigned long long acc[NP][4] = {};   // bit-zero == (0.f, 0.f)

    float4 pa0, pa1;
    float  pb[BL];

    auto loadA = [&](int kt) {
        const float* A = A1; int Ks = K1;
        if (K2 > 0 && kt >= K1) { A = A2; Ks = K2; kt -= K1; }
        if (gn < NN) {
            const float* p = A + (size_t)gn * Ks + kt + akk;
            pa0 = *(const float4*)p;
            pa1 = *(const float4*)(p + 4);
        } else {
            pa0 = make_float4(0.f, 0.f, 0.f, 0.f);
            pa1 = pa0;
        }
    };
    auto loadB = [&](int kt) {
        const float* B = B1;
        if (K2 > 0 && kt >= K1) { B = B2; kt -= K1; }
        #pragma unroll
        for (int i = 0; i < BL; i++) {
            int idx = tid + i * 256;
            int kr = idx / OC, c = idx % OC;
            pb[i] = B[(size_t)(kt + kr) * OC + c];
        }
    };

    loadA(0); loadB(0);

    for (int kt = 0; kt < K; kt += BK) {
        // commit prefetched tile to smem
        #pragma unroll
        for (int j = 0; j < 4; j++) sA[akk + j][an]     = (&pa0.x)[j];
        #pragma unroll
        for (int j = 0; j < 4; j++) sA[akk + 4 + j][an] = (&pa1.x)[j];
        #pragma unroll
        for (int i = 0; i < BL; i++) {
            int idx = tid + i * 256;
            int kr = idx / OC, c = idx % OC;
            sB2[kr][c] = pack2(pb[i], pb[i]);
        }
        __syncthreads();

        // prefetch next tile (gmem latency hidden by the math below)
        if (kt + BK < K) { loadA(kt + BK); loadB(kt + BK); }

        #pragma unroll
        for (int k = 0; k < BK; k++) {
            unsigned long long ap2[NP];
            {
                ulonglong2 a01 = *(const ulonglong2*)&sA[k][ty * TM];
                ap2[0] = a01.x; ap2[1] = a01.y;
                if constexpr (TM == 8) {
                    ulonglong2 a23 = *((const ulonglong2*)&sA[k][ty * TM] + 1);
                    ap2[2] = a23.x; ap2[3] = a23.y;
                }
            }
            ulonglong2 b01 = *(const ulonglong2*)&sB2[k][tx * 4];
            ulonglong2 b23 = *((const ulonglong2*)&sB2[k][tx * 4] + 1);
            unsigned long long bd[4] = {b01.x, b01.y, b23.x, b23.y};
            #pragma unroll
            for (int p = 0; p < NP; p++) {
                #pragma unroll
                for (int c = 0; c < 4; c++) ffma2(acc[p][c], ap2[p], bd[c]);
            }
        }
        __syncthreads();
    }

    const float4 bv = *(const float4*)&bias[tx * 4];
    #pragma unroll
    for (int p = 0; p < NP; p++) {
        int r0 = n0 + ty * TM + 2 * p;
        float4 o0, o1;
        unpack2(acc[p][0], o0.x, o1.x);
        unpack2(acc[p][1], o0.y, o1.y);
        unpack2(acc[p][2], o0.z, o1.z);
        unpack2(acc[p][3], o0.w, o1.w);
        o0.x += bv.x; o0.y += bv.y; o0.z += bv.z; o0.w += bv.w;
        o1.x += bv.x; o1.y += bv.y; o1.z += bv.z; o1.w += bv.w;
        if (RELU) {
            o0.x = fmaxf(o0.x, 0.f); o0.y = fmaxf(o0.y, 0.f);
            o0.z = fmaxf(o0.z, 0.f); o0.w = fmaxf(o0.w, 0.f);
            o1.x = fmaxf(o1.x, 0.f); o1.y = fmaxf(o1.y, 0.f);
            o1.z = fmaxf(o1.z, 0.f); o1.w = fmaxf(o1.w, 0.f);
        }
        if (r0 < NN)     *(float4*)&C[(size_t)r0 * OC + tx * 4]       = o0;
        if (r0 + 1 < NN) *(float4*)&C[(size_t)(r0 + 1) * OC + tx * 4] = o1;
    }
}

// ---------------- launch ------------------------------------------------------
extern "C" void kernel_launch(void* const* d_in, const int* in_sizes, int n_in,
                              void* d_out, int out_size) {
    const float* x     = (const float*)d_in[0];
    const void*  ei    = d_in[1];
    const float* W_l1  = (const float*)d_in[2];
    const float* b_l1  = (const float*)d_in[3];
    const float* W_r1  = (const float*)d_in[4];
    const float* W_l2  = (const float*)d_in[5];
    const float* b_l2  = (const float*)d_in[6];
    const float* W_r2  = (const float*)d_in[7];
    const float* W_out = (const float*)d_in[8];
    const float* b_out = (const float*)d_in[9];
    float* out = (float*)d_out;

    long long twoE = (long long)in_sizes[1];
    int E = (int)(twoE / 2);

    float *agg1, *agg2, *h1, *h2;
    cudaGetSymbolAddress((void**)&agg1, g_agg1);
    cudaGetSymbolAddress((void**)&agg2, g_agg2);
    cudaGetSymbolAddress((void**)&h1,   g_h1);
    cudaGetSymbolAddress((void**)&h2,   g_h2);

    const int NB = (NN + 63) / 64;   // 782 GEMM blocks

    // ---- build CSR once (shared by both layers) ----
    k_zero   <<<SCAN_BLKS + 1, 256>>>((const int*)ei, twoE);
    k_count  <<<1024, 256>>>(ei, E);
    k_scan1  <<<SCAN_BLKS, 256>>>();
    k_scan2  <<<1, 256>>>();
    k_scan3  <<<SCAN_BLKS, 256>>>();
    k_scatter<<<2048, 256>>>(ei, E);

    // layer 1: agg1 = mean_nbr x ;  h1 = relu(agg1*W_l1 + x*W_r1 + b_l1)
    k_gather<D_IN><<<(NN * (D_IN / 4) + 255) / 256, 256>>>(x, agg1);
    k_fused<D_IN, D_IN, HID, true><<<NB, 256>>>(agg1, x, W_l1, W_r1, b_l1, h1);

    // layer 2: agg2 = mean_nbr h1 ; h2 = relu(agg2*W_l2 + h1*W_r2 + b_l2)
    k_gather<HID><<<(NN * (HID / 4) + 255) / 256, 256>>>(h1, agg2);
    k_fused<HID, HID, HID, true><<<NB, 256>>>(agg2, h1, W_l2, W_r2, b_l2, h2);

    // output projection (no relu)
    k_fused<HID, 0, D_OUT, false><<<NB, 256>>>(h2, nullptr, W_out, nullptr, b_out, out);
}

// round 16
// speedup vs baseline: 1.5285x; 1.1834x over previous
#include <cuda_runtime.h>

#define NN 50000          // nodes
#define E_MAX 1600000
#define D_IN 64
#define HID 128
#define D_OUT 64
#define SCAN_BLKS ((NN + 255) / 256)   // 196

// ---------------- scratch (device globals: allocation-free rule) -------------
__device__ __align__(16) float g_agg1[NN * D_IN];   // 12.8 MB
__device__ __align__(16) float g_h1  [NN * HID];    // 25.6 MB
__device__ __align__(16) float g_agg2[NN * HID];    // 25.6 MB
__device__ __align__(16) float g_h2  [NN * HID];    // 25.6 MB
__device__ int   g_cnt[NN];
__device__ float g_inv[NN];
__device__ int   g_rowptr[NN + 1];
__device__ int   g_fill[NN];
__device__ int   g_pre[NN];          // exclusive-within-block prefix
__device__ int   g_blk[SCAN_BLKS];   // per-block totals -> exclusive offsets
__device__ int   g_csr[E_MAX];
__device__ int   g_detect;   // 1 if edge_index is int32, 0 if int64

// ---------------- packed f32x2 helpers (FFMA2 on sm_103a) --------------------
__device__ __forceinline__ unsigned long long pack2(float lo, float hi) {
    unsigned long long r;
    asm("mov.b64 %0, {%1, %2};" : "=l"(r) : "f"(lo), "f"(hi));
    return r;
}
__device__ __forceinline__ void unpack2(unsigned long long v, float& lo, float& hi) {
    asm("mov.b64 {%0, %1}, %2;" : "=f"(lo), "=f"(hi) : "l"(v));
}
__device__ __forceinline__ void ffma2(unsigned long long& d,
                                      unsigned long long a, unsigned long long b) {
    asm("fma.rn.f32x2 %0, %1, %2, %0;" : "+l"(d) : "l"(a), "l"(b));
}

// ---------------- helpers ----------------------------------------------------
__device__ __forceinline__ int edge_at(const void* ei, long long i, bool is64) {
    if (is64) return (int)__ldg(((const long long*)ei) + i);
    return __ldg(((const int*)ei) + i);
}

// ---------------- zero counters + int32/int64 detection -----------------------
// Block SCAN_BLKS does the dtype detection alone (sole writer of g_detect).
// If buffer is int64 (values < 2^31, nonneg), every odd 32-bit word is 0.
__global__ void k_zero(const int* __restrict__ w, long long twoE) {
    if (blockIdx.x == SCAN_BLKS) {
        int t = threadIdx.x;
        int v = 0;
        #pragma unroll
        for (int s = 0; s < 8; s++) {
            long long i = 2LL * (t + s * 256) + 1;
            if (i < twoE) v |= w[i];
        }
        int any = __syncthreads_or(v);
        if (t == 0) g_detect = any ? 1 : 0;
        return;
    }
    int idx = blockIdx.x * 256 + threadIdx.x;
    if (idx < NN) g_cnt[idx] = 0;
}

// ---------------- in-degree histogram ----------------------------------------
__global__ void k_count(const void* __restrict__ ei, int E) {
    bool is64 = (g_detect == 0);
    int idx = blockIdx.x * blockDim.x + threadIdx.x;
    int stride = gridDim.x * blockDim.x;
    for (int e = idx; e < E; e += stride) {
        int dst = edge_at(ei, (long long)E + e, is64);
        atomicAdd(&g_cnt[dst], 1);
    }
}

// ---------------- three-phase parallel scan of g_cnt --------------------------
__global__ __launch_bounds__(256) void k_scan1() {
    __shared__ int s[256];
    int t = threadIdx.x;
    int i = blockIdx.x * 256 + t;
    int v = (i < NN) ? g_cnt[i] : 0;
    s[t] = v;
    __syncthreads();
    #pragma unroll
    for (int off = 1; off < 256; off <<= 1) {
        int u = (t >= off) ? s[t - off] : 0;
        __syncthreads();
        s[t] += u;
        __syncthreads();
    }
    if (i < NN) g_pre[i] = s[t] - v;
    if (t == 255) g_blk[blockIdx.x] = s[255];
}

__global__ __launch_bounds__(256) void k_scan2() {
    __shared__ int s[256];
    int t = threadIdx.x;
    int v = (t < SCAN_BLKS) ? g_blk[t] : 0;
    s[t] = v;
    __syncthreads();
    #pragma unroll
    for (int off = 1; off < 256; off <<= 1) {
        int u = (t >= off) ? s[t - off] : 0;
        __syncthreads();
        s[t] += u;
        __syncthreads();
    }
    if (t < SCAN_BLKS) g_blk[t] = s[t] - v;          // exclusive offset
    if (t == 255) g_rowptr[NN] = s[255];             // total = E
}

__global__ __launch_bounds__(256) void k_scan3() {
    int i = blockIdx.x * 256 + threadIdx.x;
    if (i >= NN) return;
    int rp = g_pre[i] + g_blk[i >> 8];
    g_rowptr[i] = rp;
    g_fill[i]   = rp;
    int c = g_cnt[i];
    g_inv[i] = 1.0f / (float)(c > 1 ? c : 1);
}

// ---------------- CSR scatter (src ids into dst buckets) ----------------------
__global__ void k_scatter(const void* __restrict__ ei, int E) {
    bool is64 = (g_detect == 0);
    int idx = blockIdx.x * blockDim.x + threadIdx.x;
    int stride = gridDim.x * blockDim.x;
    for (int e = idx; e < E; e += stride) {
        int src = edge_at(ei, e, is64);
        int dst = edge_at(ei, (long long)E + e, is64);
        int pos = atomicAdd(&g_fill[dst], 1);
        g_csr[pos] = src;
    }
}

// ---------------- CSR gather-MEAN aggregation ---------------------------------
template <int D>
__global__ void k_gather(const float* __restrict__ feat, float* __restrict__ out) {
    constexpr int TPE = D / 4;                    // 16 or 32 lanes per node
    int gid  = blockIdx.x * blockDim.x + threadIdx.x;
    int node = gid / TPE;
    int lane = gid % TPE;
    if (node >= NN) return;
    int beg = g_rowptr[node], end = g_rowptr[node + 1];
    const float4* f4 = (const float4*)feat;
    float4 a0 = {0.f, 0.f, 0.f, 0.f};
    float4 a1 = a0, a2 = a0, a3 = a0;
    int j = beg;
    for (; j + 4 <= end; j += 4) {
        int s0 = __ldg(&g_csr[j]);
        int s1 = __ldg(&g_csr[j + 1]);
        int s2 = __ldg(&g_csr[j + 2]);
        int s3 = __ldg(&g_csr[j + 3]);
        float4 v0 = f4[(size_t)s0 * TPE + lane];
        float4 v1 = f4[(size_t)s1 * TPE + lane];
        float4 v2 = f4[(size_t)s2 * TPE + lane];
        float4 v3 = f4[(size_t)s3 * TPE + lane];
        a0.x += v0.x; a0.y += v0.y; a0.z += v0.z; a0.w += v0.w;
        a1.x += v1.x; a1.y += v1.y; a1.z += v1.z; a1.w += v1.w;
        a2.x += v2.x; a2.y += v2.y; a2.z += v2.z; a2.w += v2.w;
        a3.x += v3.x; a3.y += v3.y; a3.z += v3.z; a3.w += v3.w;
    }
    for (; j < end; j++) {
        int s = __ldg(&g_csr[j]);
        float4 v = f4[(size_t)s * TPE + lane];
        a0.x += v.x; a0.y += v.y; a0.z += v.z; a0.w += v.w;
    }
    float inv = g_inv[node];
    float4 r;
    r.x = ((a0.x + a1.x) + (a2.x + a3.x)) * inv;
    r.y = ((a0.y + a1.y) + (a2.y + a3.y)) * inv;
    r.z = ((a0.z + a1.z) + (a2.z + a3.z)) * inv;
    r.w = ((a0.w + a1.w) + (a2.w + a3.w)) * inv;
    ((float4*)out)[(size_t)node * TPE + lane] = r;
}

// ---------------- fused dual-GEMM + bias + relu (FFMA2, column-pair packing) --
// C[n, 0:OC] = act( A1[n,:K1] @ B1 + A2[n,:K2] @ B2 + bias ).
// f32x2 pairs run along OUTPUT COLUMNS: B tile stays plain fp32 in smem (a
// float4 load yields two column-pairs directly); A is stored duplicated (8B
// per value) but its reads are warp-broadcast, so the crossbar only carries
// ~256B/warp/k of B instead of 2KB of duplicated B. Thread tile: 8 rows x
// CPT cols. BN=128. Register-prefetch double buffering over virtual K=K1+K2.
template <int K1, int K2, int OC, bool RELU>
__global__ __launch_bounds__(256) void k_fused(
    const float* __restrict__ A1, const float* __restrict__ A2,
    const float* __restrict__ B1, const float* __restrict__ B2,
    const float* __restrict__ bias, float* __restrict__ C)
{
    constexpr int BN = 128, BK = 32;
    constexpr int K   = K1 + K2;
    constexpr int CPT = OC / 16;          // cols/thread: 8 (OC=128) or 4 (OC=64)
    constexpr int NQ  = CPT / 2;          // col-pairs/thread: 4 or 2
    constexpr int CG  = 16;               // column groups
    constexpr int TM  = 8;                // rows/thread (BN / (256/CG))
    constexpr int NB4 = (BK * OC) / 1024; // B float4 per thread: 4 or 2
    __shared__ __align__(16) unsigned long long sA2[BK][BN];  // dup-packed A, 32KB
    __shared__ __align__(16) float sB[BK][OC];                // plain B

    const int n0  = blockIdx.x * BN;
    const int tid = threadIdx.x;
    const int tx  = tid % CG;
    const int ty  = tid / CG;

    const int arow = tid >> 1;            // A row within tile (2 threads/row)
    const int akk  = (tid & 1) * 16;      // A k-offset within tile
    const int gn   = n0 + arow;

    unsigned long long acc[TM][NQ] = {};  // bit-zero == (0.f, 0.f)

    float4 pa[4];        // 16 A floats
    float4 pbv[NB4];     // B tile slice

    auto loadA = [&](int kt) {
        const float* A = A1; int Ks = K1;
        if (K2 > 0 && kt >= K1) { A = A2; Ks = K2; kt -= K1; }
        if (gn < NN) {
            const float4* p = (const float4*)(A + (size_t)gn * Ks + kt + akk);
            pa[0] = p[0]; pa[1] = p[1]; pa[2] = p[2]; pa[3] = p[3];
        } else {
            pa[0] = make_float4(0.f, 0.f, 0.f, 0.f);
            pa[1] = pa[0]; pa[2] = pa[0]; pa[3] = pa[0];
        }
    };
    auto loadB = [&](int kt) {
        const float* B = B1;
        if (K2 > 0 && kt >= K1) { B = B2; kt -= K1; }
        const float4* B4 = (const float4*)B;
        #pragma unroll
        for (int i = 0; i < NB4; i++) {
            int idx4 = tid + i * 256;
            int kr = idx4 / (OC / 4), c4 = idx4 % (OC / 4);
            pbv[i] = B4[(size_t)(kt + kr) * (OC / 4) + c4];
        }
    };

    loadA(0); loadB(0);

    for (int kt = 0; kt < K; kt += BK) {
        // commit prefetched tile to smem (A duplicated into both f32x2 halves)
        #pragma unroll
        for (int i = 0; i < 4; i++) {
            #pragma unroll
            for (int j = 0; j < 4; j++) {
                float v = (&pa[i].x)[j];
                sA2[akk + i * 4 + j][arow] = pack2(v, v);
            }
        }
        #pragma unroll
        for (int i = 0; i < NB4; i++) {
            int idx4 = tid + i * 256;
            int kr = idx4 / (OC / 4), c4 = idx4 % (OC / 4);
            *(float4*)&sB[kr][c4 * 4] = pbv[i];
        }
        __syncthreads();

        // prefetch next tile (gmem latency hidden by the math below)
        if (kt + BK < K) { loadA(kt + BK); loadB(kt + BK); }

        #pragma unroll
        for (int k = 0; k < BK; k++) {
            unsigned long long a2[TM];
            #pragma unroll
            for (int m = 0; m < TM; m += 2) {
                ulonglong2 t = *(const ulonglong2*)&sA2[k][ty * TM + m];
                a2[m] = t.x; a2[m + 1] = t.y;
            }
            unsigned long long bq[NQ];
            #pragma unroll
            for (int q = 0; q < NQ; q += 2) {
                ulonglong2 t = *(const ulonglong2*)&sB[k][tx * CPT + q * 2];
                bq[q] = t.x; bq[q + 1] = t.y;
            }
            #pragma unroll
            for (int m = 0; m < TM; m++) {
                #pragma unroll
                for (int q = 0; q < NQ; q++) ffma2(acc[m][q], a2[m], bq[q]);
            }
        }
        __syncthreads();
    }

    // epilogue: bias + relu + store
    float bb[CPT];
    #pragma unroll
    for (int q = 0; q < NQ; q += 2) {
        float4 b4 = *(const float4*)&bias[tx * CPT + q * 2];
        bb[q * 2] = b4.x; bb[q * 2 + 1] = b4.y; bb[q * 2 + 2] = b4.z; bb[q * 2 + 3] = b4.w;
    }
    #pragma unroll
    for (int m = 0; m < TM; m++) {
        int row = n0 + ty * TM + m;
        if (row >= NN) break;
        float o[CPT];
        #pragma unroll
        for (int q = 0; q < NQ; q++) unpack2(acc[m][q], o[2 * q], o[2 * q + 1]);
        #pragma unroll
        for (int c = 0; c < CPT; c++) {
            float v = o[c] + bb[c];
            if (RELU) v = fmaxf(v, 0.f);
            o[c] = v;
        }
        float* dst = &C[(size_t)row * OC + tx * CPT];
        #pragma unroll
        for (int q = 0; q < NQ; q += 2)
            *(float4*)(dst + q * 2) = make_float4(o[q*2], o[q*2+1], o[q*2+2], o[q*2+3]);
    }
}

// ---------------- launch ------------------------------------------------------
extern "C" void kernel_launch(void* const* d_in, const int* in_sizes, int n_in,
                              void* d_out, int out_size) {
    const float* x     = (const float*)d_in[0];
    const void*  ei    = d_in[1];
    const float* W_l1  = (const float*)d_in[2];
    const float* b_l1  = (const float*)d_in[3];
    const float* W_r1  = (const float*)d_in[4];
    const float* W_l2  = (const float*)d_in[5];
    const float* b_l2  = (const float*)d_in[6];
    const float* W_r2  = (const float*)d_in[7];
    const float* W_out = (const float*)d_in[8];
    const float* b_out = (const float*)d_in[9];
    float* out = (float*)d_out;

    long long twoE = (long long)in_sizes[1];
    int E = (int)(twoE / 2);

    float *agg1, *agg2, *h1, *h2;
    cudaGetSymbolAddress((void**)&agg1, g_agg1);
    cudaGetSymbolAddress((void**)&agg2, g_agg2);
    cudaGetSymbolAddress((void**)&h1,   g_h1);
    cudaGetSymbolAddress((void**)&h2,   g_h2);

    const int NB = (NN + 127) / 128;   // 391 GEMM blocks

    // ---- build CSR once (shared by both layers) ----
    k_zero   <<<SCAN_BLKS + 1, 256>>>((const int*)ei, twoE);
    k_count  <<<1024, 256>>>(ei, E);
    k_scan1  <<<SCAN_BLKS, 256>>>();
    k_scan2  <<<1, 256>>>();
    k_scan3  <<<SCAN_BLKS, 256>>>();
    k_scatter<<<2048, 256>>>(ei, E);

    // layer 1: agg1 = mean_nbr x ;  h1 = relu(agg1*W_l1 + x*W_r1 + b_l1)
    k_gather<D_IN><<<(NN * (D_IN / 4) + 255) / 256, 256>>>(x, agg1);
    k_fused<D_IN, D_IN, HID, true><<<NB, 256>>>(agg1, x, W_l1, W_r1, b_l1, h1);

    // layer 2: agg2 = mean_nbr h1 ; h2 = relu(agg2*W_l2 + h1*W_r2 + b_l2)
    k_gather<HID><<<(NN * (HID / 4) + 255) / 256, 256>>>(h1, agg2);
    k_fused<HID, HID, HID, true><<<NB, 256>>>(agg2, h1, W_l2, W_r2, b_l2, h2);

    // output projection (no relu)
    k_fused<HID, 0, D_OUT, false><<<NB, 256>>>(h2, nullptr, W_out, nullptr, b_out, out);
}